// round 3
// baseline (speedup 1.0000x reference)
#include <cuda_runtime.h>
#include <math.h>
#include <stdint.h>

// Problem constants (fixed by the dataset)
#define NN 50000
#define EE 500000
#define FF 64
#define HH 4
#define HF 256          // H*F
#define TOT (EE + NN)   // edges + self loops
#define NTILE ((TOT + 63) / 64)
#define ASTR 66         // u64 stride per k-row of sA (64 edges + pad, 16B-aligned rows)

// ---------------- device scratch ----------------
__device__ float    g_xl[NN * HF];
__device__ float    g_xr[NN * HF];
__device__ float    g_loop[NN * FF];
__device__ float    g_cnt[NN];
__device__ float    g_alpha[(size_t)TOT * HH];
__device__ unsigned g_amax[NN * HH];
__device__ float    g_denom[NN * HH];
__device__ float    g_outpre[NN * FF];
__device__ float    g_bnsum[FF];
__device__ float    g_bnsq[FF];

// ---------------- helpers ----------------
__device__ __forceinline__ unsigned fenc(float f) {
    unsigned u = __float_as_uint(f);
    return (u & 0x80000000u) ? ~u : (u | 0x80000000u);
}
__device__ __forceinline__ float fdec(unsigned u) {
    return (u & 0x80000000u) ? __uint_as_float(u & 0x7fffffffu)
                             : __uint_as_float(~u);
}
__device__ __forceinline__ void red2(float* p, float a, float b) {
    unsigned long long gp = __cvta_generic_to_global(p);
    asm volatile("red.global.add.v2.f32 [%0], {%1, %2};"
                 :: "l"(gp), "f"(a), "f"(b) : "memory");
}
__device__ __forceinline__ float lrelu(float v) {
    return v > 0.f ? v : 0.2f * v;
}
__device__ __forceinline__ void fma2(unsigned long long& acc,
                                     unsigned long long a, unsigned long long b) {
    asm("fma.rn.f32x2 %0, %1, %2, %0;" : "+l"(acc) : "l"(a), "l"(b));
}
__device__ __forceinline__ unsigned long long add2(unsigned long long a,
                                                   unsigned long long b) {
    unsigned long long r;
    asm("add.rn.f32x2 %0, %1, %2;" : "=l"(r) : "l"(a), "l"(b));
    return r;
}
__device__ __forceinline__ void unpack2(unsigned long long v, float& lo, float& hi) {
    asm("mov.b64 {%0, %1}, %2;" : "=f"(lo), "=f"(hi) : "l"(v));
}
__device__ __forceinline__ uint32_t s2u32(const void* p) {
    uint32_t a;
    asm("{ .reg .u64 t; cvta.to.shared.u64 t, %1; cvt.u32.u64 %0, t; }"
        : "=r"(a) : "l"(p));
    return a;
}
__device__ __forceinline__ void sts_dup(uint32_t addr, float v) {
    asm volatile("st.shared.v2.f32 [%0], {%1, %1};" :: "r"(addr), "f"(v) : "memory");
}

// ---------------- K0: zero accumulators ----------------
__global__ void k_zero() {
    int i = blockIdx.x * blockDim.x + threadIdx.x;
    if (i < NN * FF) { g_loop[i] = 0.f; g_outpre[i] = 0.f; }
    if (i < NN * HH) { g_amax[i] = 0u; g_denom[i] = 0.f; }
    if (i < NN)      { g_cnt[i] = 0.f; }
    if (i < FF)      { g_bnsum[i] = 0.f; g_bnsq[i] = 0.f; }
}

// ---------------- K1: x_l / x_r linear ----------------
__global__ void __launch_bounds__(256) k_lin(
    const float* __restrict__ x,
    const float* __restrict__ Wl, const float* __restrict__ bl,
    const float* __restrict__ Wr, const float* __restrict__ br)
{
    __shared__ float xs[32 * 64];
    __shared__ float ws[64 * 128];
    int tid  = threadIdx.x;
    int row0 = blockIdx.x * 32;
    int cb   = blockIdx.y * 128;
    const float* W = (cb < 256) ? Wl : Wr;
    const float* B = (cb < 256) ? bl : br;
    float*       D = (cb < 256) ? g_xl : g_xr;
    int wcb = cb & 255;

    for (int i = tid; i < 32 * 64; i += 256) {
        int r = i >> 6, k = i & 63;
        int row = row0 + r;
        xs[i] = (row < NN) ? x[row * 64 + k] : 0.f;
    }
    for (int i = tid; i < 64 * 128; i += 256) {
        int k = i >> 7, c = i & 127;
        ws[i] = W[k * 256 + wcb + c];
    }
    __syncthreads();

    int tx = tid & 31, ty = tid >> 5;
    float acc[4][4];
#pragma unroll
    for (int rr = 0; rr < 4; rr++)
#pragma unroll
        for (int cc = 0; cc < 4; cc++) acc[rr][cc] = 0.f;

    for (int k = 0; k < 64; k++) {
        float b0 = ws[k * 128 + tx];
        float b1 = ws[k * 128 + tx + 32];
        float b2 = ws[k * 128 + tx + 64];
        float b3 = ws[k * 128 + tx + 96];
#pragma unroll
        for (int rr = 0; rr < 4; rr++) {
            float a = xs[(ty + 8 * rr) * 64 + k];
            acc[rr][0] += a * b0;
            acc[rr][1] += a * b1;
            acc[rr][2] += a * b2;
            acc[rr][3] += a * b3;
        }
    }
#pragma unroll
    for (int rr = 0; rr < 4; rr++) {
        int row = row0 + ty + 8 * rr;
        if (row < NN) {
#pragma unroll
            for (int cc = 0; cc < 4; cc++) {
                int c = tx + 32 * cc;
                D[row * 256 + wcb + c] = acc[rr][cc] + B[wcb + c];
            }
        }
    }
}

// ---------------- K2: self-loop edge_attr sums + in-degree counts ----------------
__global__ void k_loopstats(const int* __restrict__ ei, const float* __restrict__ ea) {
    int gw   = (blockIdx.x * blockDim.x + threadIdx.x) >> 5;
    int lane = threadIdx.x & 31;
    if (gw >= EE) return;
    int dst = ei[EE + gw];
    const float* a = ea + (size_t)gw * 64;
    float2 v = *(const float2*)(a + lane * 2);
    red2(&g_loop[dst * 64 + lane * 2], v.x, v.y);
    if (lane == 0) atomicAdd(&g_cnt[dst], 1.0f);
}

// ---------------- K3a: fused SGEMM-tile attention scores + segment max ----------
// Persistent blocks. W_e resident in smem for the block's lifetime. Each tile:
// 64 edges x 256 feats. Warp w: edges w*8..w*8+7; lane: 8 feats (lane*8..+7).
// acc is feature-pair packed f32x2; ea staged DUPLICATED so the inner loop is
// pure 6x LDS.128 + 32x fma.rn.f32x2 per k.
extern __shared__ unsigned char k3_raw[];
// layout: sW float[64*256] @0 (65536B) | sA u64[64*ASTR] @65536 (33792B)
//         sSrc int[64] | sDst int[64] | sAtt float[256]
#define K3_SMEM (65536 + 64 * ASTR * 8 + 256 + 256 + 1024)

__global__ void __launch_bounds__(256, 2) k_alpha(
    const int* __restrict__ ei, const float* __restrict__ ea,
    const float* __restrict__ We, const float* __restrict__ att)
{
    float* sW = (float*)k3_raw;
    unsigned long long* sA = (unsigned long long*)(k3_raw + 65536);
    int* sSrc  = (int*)(k3_raw + 65536 + 64 * ASTR * 8);
    int* sDst  = sSrc + 64;
    float* sAtt = (float*)(sDst + 64);

    int tid = threadIdx.x;
    int lane = tid & 31, wid = tid >> 5;
    uint32_t sA_u = s2u32(sA);

    for (int i = tid; i < 64 * 256; i += 256) sW[i] = We[i];
    if (tid < 256) sAtt[tid] = att[tid];
    __syncthreads();

    float attr[8];
#pragma unroll
    for (int j = 0; j < 8; j++) attr[j] = sAtt[lane * 8 + j];

    int tex = tid & 63;     // staging edge slot
    int kq  = tid >> 6;     // staging k-quarter (16 k's each)

    for (int tile = blockIdx.x; tile < NTILE; tile += gridDim.x) {
        int base = tile * 64;

        // ---- stage indices ----
        if (tid < 64) {
            int te = base + tid;
            int s, d;
            if (te >= TOT)     { s = 0; d = 0; }
            else if (te < EE)  { s = ei[te]; d = ei[EE + te]; }
            else               { s = d = te - EE; }
            sSrc[tid] = s; sDst[tid] = d;
        }
        // ---- stage ea tile, duplicated ----
        {
            int te = base + tex;
            if (te >= TOT) te = TOT - 1;
            const float* src;
            float scale = 1.f;
            if (te < EE) {
                src = ea + (size_t)te * 64;
            } else {
                int n = te - EE;
                src = g_loop + (size_t)n * 64;
                float c = g_cnt[n];
                scale = 1.f / ((c < 1.f) ? 1.f : c);
            }
#pragma unroll
            for (int b = 0; b < 4; b++) {
                int k0 = kq * 16 + b * 4;
                float4 v = *(const float4*)(src + k0);
                v.x *= scale; v.y *= scale; v.z *= scale; v.w *= scale;
                uint32_t a0 = sA_u + (uint32_t)(((k0 + 0) * ASTR + tex) * 8);
                sts_dup(a0, v.x);
                sts_dup(sA_u + (uint32_t)(((k0 + 1) * ASTR + tex) * 8), v.y);
                sts_dup(sA_u + (uint32_t)(((k0 + 2) * ASTR + tex) * 8), v.z);
                sts_dup(sA_u + (uint32_t)(((k0 + 3) * ASTR + tex) * 8), v.w);
            }
        }
        __syncthreads();

        // ---- mainloop: acc[e][fp] += ea_dup[e] * w[fp] ----
        unsigned long long acc[8][4];
#pragma unroll
        for (int e = 0; e < 8; e++)
#pragma unroll
            for (int j = 0; j < 4; j++) acc[e][j] = 0ull;

        const float* wp = sW + lane * 8;
        const unsigned long long* ap = sA + wid * 8;
#pragma unroll 4
        for (int k = 0; k < 64; k++) {
            ulonglong2 wA = *(const ulonglong2*)(wp + k * 256);
            ulonglong2 wB = *(const ulonglong2*)(wp + k * 256 + 4);
            ulonglong2 a01 = *(const ulonglong2*)(ap + k * ASTR);
            ulonglong2 a23 = *(const ulonglong2*)(ap + k * ASTR + 2);
            ulonglong2 a45 = *(const ulonglong2*)(ap + k * ASTR + 4);
            ulonglong2 a67 = *(const ulonglong2*)(ap + k * ASTR + 6);
            fma2(acc[0][0], a01.x, wA.x); fma2(acc[0][1], a01.x, wA.y);
            fma2(acc[0][2], a01.x, wB.x); fma2(acc[0][3], a01.x, wB.y);
            fma2(acc[1][0], a01.y, wA.x); fma2(acc[1][1], a01.y, wA.y);
            fma2(acc[1][2], a01.y, wB.x); fma2(acc[1][3], a01.y, wB.y);
            fma2(acc[2][0], a23.x, wA.x); fma2(acc[2][1], a23.x, wA.y);
            fma2(acc[2][2], a23.x, wB.x); fma2(acc[2][3], a23.x, wB.y);
            fma2(acc[3][0], a23.y, wA.x); fma2(acc[3][1], a23.y, wA.y);
            fma2(acc[3][2], a23.y, wB.x); fma2(acc[3][3], a23.y, wB.y);
            fma2(acc[4][0], a45.x, wA.x); fma2(acc[4][1], a45.x, wA.y);
            fma2(acc[4][2], a45.x, wB.x); fma2(acc[4][3], a45.x, wB.y);
            fma2(acc[5][0], a45.y, wA.x); fma2(acc[5][1], a45.y, wA.y);
            fma2(acc[5][2], a45.y, wB.x); fma2(acc[5][3], a45.y, wB.y);
            fma2(acc[6][0], a67.x, wA.x); fma2(acc[6][1], a67.x, wA.y);
            fma2(acc[6][2], a67.x, wB.x); fma2(acc[6][3], a67.x, wB.y);
            fma2(acc[7][0], a67.y, wA.x); fma2(acc[7][1], a67.y, wA.y);
            fma2(acc[7][2], a67.y, wB.x); fma2(acc[7][3], a67.y, wB.y);
        }

        // ---- epilogue: +xl+xr, lrelu, att-dot, head reduce, store + amax ----
        int e8 = wid * 8;
#pragma unroll
        for (int e = 0; e < 8; e++) {
            int te = base + e8 + e;
            int s = sSrc[e8 + e], d = sDst[e8 + e];
            const ulonglong2* xl = (const ulonglong2*)(g_xl + (size_t)s * 256 + lane * 8);
            const ulonglong2* xr = (const ulonglong2*)(g_xr + (size_t)d * 256 + lane * 8);
            ulonglong2 l0 = xl[0], l1 = xl[1];
            ulonglong2 r0 = xr[0], r1 = xr[1];
            unsigned long long t0 = add2(add2(acc[e][0], l0.x), r0.x);
            unsigned long long t1 = add2(add2(acc[e][1], l0.y), r0.y);
            unsigned long long t2 = add2(add2(acc[e][2], l1.x), r1.x);
            unsigned long long t3 = add2(add2(acc[e][3], l1.y), r1.y);
            float f0, f1, f2, f3, f4, f5, f6, f7;
            unpack2(t0, f0, f1); unpack2(t1, f2, f3);
            unpack2(t2, f4, f5); unpack2(t3, f6, f7);
            float p = lrelu(f0) * attr[0] + lrelu(f1) * attr[1]
                    + lrelu(f2) * attr[2] + lrelu(f3) * attr[3]
                    + lrelu(f4) * attr[4] + lrelu(f5) * attr[5]
                    + lrelu(f6) * attr[6] + lrelu(f7) * attr[7];
            p += __shfl_xor_sync(0xffffffffu, p, 1);
            p += __shfl_xor_sync(0xffffffffu, p, 2);
            p += __shfl_xor_sync(0xffffffffu, p, 4);
            if (te < TOT && (lane & 7) == 0) {
                int h = lane >> 3;
                g_alpha[(size_t)te * 4 + h] = p;
                atomicMax(&g_amax[d * 4 + h], fenc(p));
            }
        }
        __syncthreads();   // protect sA/sSrc before next tile's staging
    }
}

// ---------------- K3b: exp(alpha - max) and denominator ----------------
__global__ void k_exp(const int* __restrict__ ei) {
    int e = blockIdx.x * blockDim.x + threadIdx.x;
    if (e >= TOT) return;
    int d = (e < EE) ? ei[EE + e] : (e - EE);
    float4 a = *(const float4*)&g_alpha[(size_t)e * 4];
    uint4 mu = *(const uint4*)&g_amax[d * 4];
    float e0 = __expf(a.x - fdec(mu.x));
    float e1 = __expf(a.y - fdec(mu.y));
    float e2 = __expf(a.z - fdec(mu.z));
    float e3 = __expf(a.w - fdec(mu.w));
    float4 r; r.x = e0; r.y = e1; r.z = e2; r.w = e3;
    *(float4*)&g_alpha[(size_t)e * 4] = r;
    red2(&g_denom[d * 4],     e0, e1);
    red2(&g_denom[d * 4 + 2], e2, e3);
}

// ---------------- K3c: weighted aggregation, fused head-mean ----------------
__global__ void k_agg(const int* __restrict__ ei) {
    int gw   = (blockIdx.x * blockDim.x + threadIdx.x) >> 5;
    int lane = threadIdx.x & 31;
    if (gw >= TOT) return;
    int s, d;
    if (gw < EE) { s = ei[gw]; d = ei[EE + gw]; }
    else         { s = d = gw - EE; }
    float4 ex = *(const float4*)&g_alpha[(size_t)gw * 4];
    float4 dn = *(const float4*)&g_denom[d * 4];
    float w0 = 0.25f * ex.x / (dn.x + 1e-16f);
    float w1 = 0.25f * ex.y / (dn.y + 1e-16f);
    float w2 = 0.25f * ex.z / (dn.z + 1e-16f);
    float w3 = 0.25f * ex.w / (dn.w + 1e-16f);
    const float* xl = g_xl + (size_t)s * 256;
    int f2 = lane * 2;
    float2 v0 = *(const float2*)(xl + f2);
    float2 v1 = *(const float2*)(xl + 64 + f2);
    float2 v2 = *(const float2*)(xl + 128 + f2);
    float2 v3 = *(const float2*)(xl + 192 + f2);
    float c0 = w0 * v0.x + w1 * v1.x + w2 * v2.x + w3 * v3.x;
    float c1 = w0 * v0.y + w1 * v1.y + w2 * v2.y + w3 * v3.y;
    red2(&g_outpre[d * 64 + f2], c0, c1);
}

// ---------------- K4a: BN statistics ----------------
__global__ void __launch_bounds__(256) k_bnstats(const float* __restrict__ bias) {
    int tid = threadIdx.x;
    int f = tid & 63, rg = tid >> 6;
    float b = bias[f];
    float s = 0.f, s2 = 0.f;
    for (int r = blockIdx.x * 4 + rg; r < NN; r += gridDim.x * 4) {
        float v = g_outpre[r * 64 + f] + b;
        s += v; s2 += v * v;
    }
    __shared__ float sh[2][4][64];
    sh[0][rg][f] = s;
    sh[1][rg][f] = s2;
    __syncthreads();
    if (tid < 64) {
        float ts = sh[0][0][tid] + sh[0][1][tid] + sh[0][2][tid] + sh[0][3][tid];
        float tq = sh[1][0][tid] + sh[1][1][tid] + sh[1][2][tid] + sh[1][3][tid];
        atomicAdd(&g_bnsum[tid], ts);
        atomicAdd(&g_bnsq[tid], tq);
    }
}

// ---------------- K4b: BN apply + ReLU ----------------
__global__ void k_bnapply(const float* __restrict__ bias,
                          const float* __restrict__ gamma,
                          const float* __restrict__ beta,
                          float* __restrict__ out) {
    int i = blockIdx.x * blockDim.x + threadIdx.x;
    if (i >= NN * FF) return;
    int f = i & 63;
    const float invn = 1.0f / (float)NN;
    float mu  = g_bnsum[f] * invn;
    float var = g_bnsq[f] * invn - mu * mu;
    float v = g_outpre[i] + bias[f];
    float o = gamma[f] * (v - mu) * rsqrtf(var + 1e-5f) + beta[f];
    out[i] = (o > 0.f) ? o : 0.f;
}

// ---------------- launch ----------------
extern "C" void kernel_launch(void* const* d_in, const int* in_sizes, int n_in,
                              void* d_out, int out_size) {
    const float* x     = (const float*)d_in[0];
    const int*   ei    = (const int*)d_in[1];
    const float* ea    = (const float*)d_in[2];
    const float* Wl    = (const float*)d_in[3];
    const float* bl    = (const float*)d_in[4];
    const float* Wr    = (const float*)d_in[5];
    const float* br    = (const float*)d_in[6];
    const float* We    = (const float*)d_in[7];
    const float* att   = (const float*)d_in[8];
    const float* bias  = (const float*)d_in[9];
    const float* gamma = (const float*)d_in[10];
    const float* beta  = (const float*)d_in[11];
    float* out = (float*)d_out;

    cudaFuncSetAttribute(k_alpha, cudaFuncAttributeMaxDynamicSharedMemorySize, K3_SMEM);

    k_zero<<<(NN * FF + 255) / 256, 256>>>();

    dim3 g1((NN + 31) / 32, 4);
    k_lin<<<g1, 256>>>(x, Wl, bl, Wr, br);

    k_loopstats<<<(EE * 32 + 255) / 256, 256>>>(ei, ea);

    // local launch index 3 -> ncu's profiled slot
    k_alpha<<<296, 256, K3_SMEM>>>(ei, ea, We, att);

    k_exp<<<(TOT + 255) / 256, 256>>>(ei);
    k_agg<<<((size_t)TOT * 32 + 255) / 256, 256>>>(ei);

    k_bnstats<<<128, 256>>>(bias);
    k_bnapply<<<(NN * FF + 255) / 256, 256>>>(bias, gamma, beta, out);
}

// round 4
// speedup vs baseline: 1.0346x; 1.0346x over previous
#include <cuda_runtime.h>
#include <math.h>
#include <stdint.h>

// Problem constants (fixed by the dataset)
#define NN 50000
#define EE 500000
#define FF 64
#define HH 4
#define HF 256          // H*F
#define TOT (EE + NN)   // edges + self loops
#define NTILE ((TOT + 63) / 64)
#define ASTR 72         // float stride per k-row of sA (64 edges + pad, 16B-aligned)

// ---------------- device scratch ----------------
__device__ float    g_xl[NN * HF];
__device__ float    g_xr[NN * HF];
__device__ float    g_loop[NN * FF];
__device__ float    g_cnt[NN];
__device__ float    g_alpha[(size_t)TOT * HH];
__device__ unsigned g_amax[NN * HH];
__device__ float    g_denom[NN * HH];
__device__ float    g_outpre[NN * FF];
__device__ float    g_bnsum[FF];
__device__ float    g_bnsq[FF];

// ---------------- helpers ----------------
__device__ __forceinline__ unsigned fenc(float f) {
    unsigned u = __float_as_uint(f);
    return (u & 0x80000000u) ? ~u : (u | 0x80000000u);
}
__device__ __forceinline__ float fdec(unsigned u) {
    return (u & 0x80000000u) ? __uint_as_float(u & 0x7fffffffu)
                             : __uint_as_float(~u);
}
__device__ __forceinline__ void red2(float* p, float a, float b) {
    unsigned long long gp = __cvta_generic_to_global(p);
    asm volatile("red.global.add.v2.f32 [%0], {%1, %2};"
                 :: "l"(gp), "f"(a), "f"(b) : "memory");
}
__device__ __forceinline__ float lrelu(float v) {
    return v > 0.f ? v : 0.2f * v;
}
__device__ __forceinline__ unsigned long long pack2(float v) {
    unsigned long long r;
    asm("mov.b64 %0, {%1, %1};" : "=l"(r) : "f"(v));
    return r;
}
__device__ __forceinline__ void fma2(unsigned long long& acc,
                                     unsigned long long a, unsigned long long b) {
    asm("fma.rn.f32x2 %0, %1, %2, %0;" : "+l"(acc) : "l"(a), "l"(b));
}
__device__ __forceinline__ void unpack2(unsigned long long v, float& lo, float& hi) {
    asm("mov.b64 {%0, %1}, %2;" : "=f"(lo), "=f"(hi) : "l"(v));
}

// ---------------- K0: zero accumulators ----------------
__global__ void k_zero() {
    int i = blockIdx.x * blockDim.x + threadIdx.x;
    if (i < NN * FF) { g_loop[i] = 0.f; g_outpre[i] = 0.f; }
    if (i < NN * HH) { g_amax[i] = 0u; g_denom[i] = 0.f; }
    if (i < NN)      { g_cnt[i] = 0.f; }
    if (i < FF)      { g_bnsum[i] = 0.f; g_bnsq[i] = 0.f; }
    if (i < TOT * HH) g_alpha[i] = 0.f;
}

// ---------------- K1: x_l / x_r linear ----------------
__global__ void __launch_bounds__(256) k_lin(
    const float* __restrict__ x,
    const float* __restrict__ Wl, const float* __restrict__ bl,
    const float* __restrict__ Wr, const float* __restrict__ br)
{
    __shared__ float xs[32 * 64];
    __shared__ float ws[64 * 128];
    int tid  = threadIdx.x;
    int row0 = blockIdx.x * 32;
    int cb   = blockIdx.y * 128;
    const float* W = (cb < 256) ? Wl : Wr;
    const float* B = (cb < 256) ? bl : br;
    float*       D = (cb < 256) ? g_xl : g_xr;
    int wcb = cb & 255;

    for (int i = tid; i < 32 * 64; i += 256) {
        int r = i >> 6, k = i & 63;
        int row = row0 + r;
        xs[i] = (row < NN) ? x[row * 64 + k] : 0.f;
    }
    for (int i = tid; i < 64 * 128; i += 256) {
        int k = i >> 7, c = i & 127;
        ws[i] = W[k * 256 + wcb + c];
    }
    __syncthreads();

    int tx = tid & 31, ty = tid >> 5;
    float acc[4][4];
#pragma unroll
    for (int rr = 0; rr < 4; rr++)
#pragma unroll
        for (int cc = 0; cc < 4; cc++) acc[rr][cc] = 0.f;

    for (int k = 0; k < 64; k++) {
        float b0 = ws[k * 128 + tx];
        float b1 = ws[k * 128 + tx + 32];
        float b2 = ws[k * 128 + tx + 64];
        float b3 = ws[k * 128 + tx + 96];
#pragma unroll
        for (int rr = 0; rr < 4; rr++) {
            float a = xs[(ty + 8 * rr) * 64 + k];
            acc[rr][0] += a * b0;
            acc[rr][1] += a * b1;
            acc[rr][2] += a * b2;
            acc[rr][3] += a * b3;
        }
    }
#pragma unroll
    for (int rr = 0; rr < 4; rr++) {
        int row = row0 + ty + 8 * rr;
        if (row < NN) {
#pragma unroll
            for (int cc = 0; cc < 4; cc++) {
                int c = tx + 32 * cc;
                D[row * 256 + wcb + c] = acc[rr][cc] + B[wcb + c];
            }
        }
    }
}

// ---------------- K2: self-loop edge_attr sums + in-degree counts ----------------
__global__ void k_loopstats(const int* __restrict__ ei, const float* __restrict__ ea) {
    int gw   = (blockIdx.x * blockDim.x + threadIdx.x) >> 5;
    int lane = threadIdx.x & 31;
    if (gw >= EE) return;
    int dst = ei[EE + gw];
    const float* a = ea + (size_t)gw * 64;
    float2 v = *(const float2*)(a + lane * 2);
    red2(&g_loop[dst * 64 + lane * 2], v.x, v.y);
    if (lane == 0) atomicAdd(&g_cnt[dst], 1.0f);
}

// ---------------- K3a: attention-score GEMM tiles (feature-split) --------------
// Block covers HALF the features (128). grid.x even/odd = half 0/1.
// Tile = 64 edges. Warp w: edges w*8..w*8+7 (edge-pair packed f32x2).
// Lane: 4 features (half*128 + lane*4). acc[4 epairs][4 feats] f32x2.
// Double-buffered sA; next tile's ea prefetched via registers before compute.
// alpha accumulated across halves via atomicAdd; segment max in k_amax after.
extern __shared__ unsigned char k3_raw[];
// layout: sW float[64*128] @0 (32768B) | sA float[2][64*ASTR] (36864B) | sIdx int[2][128]
#define K3_SW_BYTES  (64 * 128 * 4)
#define K3_SA_BYTES  (2 * 64 * ASTR * 4)
#define K3_SMEM      (K3_SW_BYTES + K3_SA_BYTES + 2 * 128 * 4)

__global__ void __launch_bounds__(256, 3) k_alpha(
    const int* __restrict__ ei, const float* __restrict__ ea,
    const float* __restrict__ We, const float* __restrict__ att)
{
    float* sW = (float*)k3_raw;
    float* sA = (float*)(k3_raw + K3_SW_BYTES);            // [2][64*ASTR]
    int*   sIdx = (int*)(k3_raw + K3_SW_BYTES + K3_SA_BYTES); // [2][128]: src[64],dst[64]

    int tid = threadIdx.x;
    int lane = tid & 31, wid = tid >> 5;
    int half = blockIdx.x & 1;
    int tile0 = blockIdx.x >> 1;
    int stride = gridDim.x >> 1;

    // load W half: [64 k][128 feats]
    {
        const float4* W4 = (const float4*)(We) + half * 32;
        float4* sW4 = (float4*)sW;
        for (int i = tid; i < 64 * 32; i += 256) {
            int k = i >> 5, c4 = i & 31;
            sW4[k * 32 + c4] = W4[k * 64 + c4];
        }
    }
    float4 attv = *(const float4*)(att + half * 128 + lane * 4);

    int tex = tid & 63;     // staging edge slot
    int kq  = tid >> 6;     // staging k-quarter (16 k's)

    // ---- prefetch lambda state ----
    float4 pf0, pf1, pf2, pf3;
    float  pscale;
    int    pfs = 0, pfd = 0;

#define LOADREG(T)                                                          \
    {                                                                       \
        int te = (T) * 64 + tex;                                            \
        if (te >= TOT) te = TOT - 1;                                        \
        const float* src_;                                                  \
        if (te < EE) { src_ = ea + (size_t)te * 64; pscale = 1.f; }         \
        else {                                                              \
            int n_ = te - EE;                                               \
            src_ = g_loop + (size_t)n_ * 64;                                \
            float c_ = g_cnt[n_];                                           \
            pscale = 1.f / ((c_ < 1.f) ? 1.f : c_);                         \
        }                                                                   \
        pf0 = *(const float4*)(src_ + kq * 16);                             \
        pf1 = *(const float4*)(src_ + kq * 16 + 4);                         \
        pf2 = *(const float4*)(src_ + kq * 16 + 8);                         \
        pf3 = *(const float4*)(src_ + kq * 16 + 12);                        \
        if (tid < 64) {                                                     \
            int t2 = (T) * 64 + tid;                                        \
            if (t2 >= TOT) t2 = TOT - 1;                                    \
            if (t2 < EE) { pfs = ei[t2]; pfd = ei[EE + t2]; }               \
            else         { pfs = pfd = t2 - EE; }                           \
        }                                                                   \
    }

#define STS_TILE(BUF)                                                       \
    {                                                                       \
        float* dst_ = sA + (BUF) * (64 * ASTR) + tex;                       \
        int kb_ = kq * 16;                                                  \
        dst_[(kb_ + 0) * ASTR] = pf0.x * pscale;                            \
        dst_[(kb_ + 1) * ASTR] = pf0.y * pscale;                            \
        dst_[(kb_ + 2) * ASTR] = pf0.z * pscale;                            \
        dst_[(kb_ + 3) * ASTR] = pf0.w * pscale;                            \
        dst_[(kb_ + 4) * ASTR] = pf1.x * pscale;                            \
        dst_[(kb_ + 5) * ASTR] = pf1.y * pscale;                            \
        dst_[(kb_ + 6) * ASTR] = pf1.z * pscale;                            \
        dst_[(kb_ + 7) * ASTR] = pf1.w * pscale;                            \
        dst_[(kb_ + 8) * ASTR] = pf2.x * pscale;                            \
        dst_[(kb_ + 9) * ASTR] = pf2.y * pscale;                            \
        dst_[(kb_ +10) * ASTR] = pf2.z * pscale;                            \
        dst_[(kb_ +11) * ASTR] = pf2.w * pscale;                            \
        dst_[(kb_ +12) * ASTR] = pf3.x * pscale;                            \
        dst_[(kb_ +13) * ASTR] = pf3.y * pscale;                            \
        dst_[(kb_ +14) * ASTR] = pf3.z * pscale;                            \
        dst_[(kb_ +15) * ASTR] = pf3.w * pscale;                            \
        if (tid < 64) {                                                     \
            sIdx[(BUF) * 128 + tid]      = pfs;                             \
            sIdx[(BUF) * 128 + 64 + tid] = pfd;                             \
        }                                                                   \
    }

    if (tile0 >= NTILE) return;
    LOADREG(tile0);
    STS_TILE(0);
    __syncthreads();

    int buf = 0;
    for (int t = tile0;;) {
        int tn = t + stride;
        bool more = (tn < NTILE);
        if (more) LOADREG(tn);   // LDGs in flight during compute

        // ---- mainloop ----
        unsigned long long acc[4][4];
#pragma unroll
        for (int p = 0; p < 4; p++)
#pragma unroll
            for (int j = 0; j < 4; j++) acc[p][j] = 0ull;

        const float* wp = sW + lane * 4;
        const float* ap = sA + buf * (64 * ASTR) + wid * 8;
#pragma unroll 4
        for (int k = 0; k < 64; k++) {
            float4 w4 = *(const float4*)(wp + k * 128);
            ulonglong2 aA = *(const ulonglong2*)(ap + k * ASTR);     // edges 0-3
            ulonglong2 aB = *(const ulonglong2*)(ap + k * ASTR + 4); // edges 4-7
            unsigned long long w0 = pack2(w4.x);
            unsigned long long w1 = pack2(w4.y);
            unsigned long long w2 = pack2(w4.z);
            unsigned long long w3 = pack2(w4.w);
            fma2(acc[0][0], aA.x, w0); fma2(acc[0][1], aA.x, w1);
            fma2(acc[0][2], aA.x, w2); fma2(acc[0][3], aA.x, w3);
            fma2(acc[1][0], aA.y, w0); fma2(acc[1][1], aA.y, w1);
            fma2(acc[1][2], aA.y, w2); fma2(acc[1][3], aA.y, w3);
            fma2(acc[2][0], aB.x, w0); fma2(acc[2][1], aB.x, w1);
            fma2(acc[2][2], aB.x, w2); fma2(acc[2][3], aB.x, w3);
            fma2(acc[3][0], aB.y, w0); fma2(acc[3][1], aB.y, w1);
            fma2(acc[3][2], aB.y, w2); fma2(acc[3][3], aB.y, w3);
        }

        // ---- epilogue: per edge +xl+xr, lrelu, att-dot, 16-lane reduce, atomicAdd
        {
            const int* sS = sIdx + buf * 128;
            const int* sD = sS + 64;
            int base = t * 64;
            int e8 = wid * 8;
            int goff = half * 128 + lane * 4;
#pragma unroll
            for (int p = 0; p < 4; p++) {
                float a0, b0, a1, b1, a2, b2, a3, b3;
                unpack2(acc[p][0], a0, b0);
                unpack2(acc[p][1], a1, b1);
                unpack2(acc[p][2], a2, b2);
                unpack2(acc[p][3], a3, b3);
#pragma unroll
                for (int eo = 0; eo < 2; eo++) {
                    int le = e8 + p * 2 + eo;
                    int te = base + le;
                    int s = sS[le], d = sD[le];
                    float4 l4 = *(const float4*)(g_xl + (size_t)s * 256 + goff);
                    float4 r4 = *(const float4*)(g_xr + (size_t)d * 256 + goff);
                    float e0 = eo ? b0 : a0;
                    float e1 = eo ? b1 : a1;
                    float e2 = eo ? b2 : a2;
                    float e3 = eo ? b3 : a3;
                    float pp = lrelu(e0 + l4.x + r4.x) * attv.x
                             + lrelu(e1 + l4.y + r4.y) * attv.y
                             + lrelu(e2 + l4.z + r4.z) * attv.z
                             + lrelu(e3 + l4.w + r4.w) * attv.w;
                    pp += __shfl_xor_sync(0xffffffffu, pp, 1);
                    pp += __shfl_xor_sync(0xffffffffu, pp, 2);
                    pp += __shfl_xor_sync(0xffffffffu, pp, 4);
                    pp += __shfl_xor_sync(0xffffffffu, pp, 8);
                    if (te < TOT && (lane & 15) == 0) {
                        int h = half * 2 + (lane >> 4);
                        atomicAdd(&g_alpha[(size_t)te * 4 + h], pp);
                    }
                }
            }
        }

        if (!more) break;
        STS_TILE(buf ^ 1);
        __syncthreads();
        buf ^= 1;
        t = tn;
    }
#undef LOADREG
#undef STS_TILE
}

// ---------------- K3a2: segment max over completed alpha ----------------
__global__ void k_amax(const int* __restrict__ ei) {
    int e = blockIdx.x * blockDim.x + threadIdx.x;
    if (e >= TOT) return;
    int d = (e < EE) ? ei[EE + e] : (e - EE);
    float4 a = *(const float4*)&g_alpha[(size_t)e * 4];
    atomicMax(&g_amax[d * 4 + 0], fenc(a.x));
    atomicMax(&g_amax[d * 4 + 1], fenc(a.y));
    atomicMax(&g_amax[d * 4 + 2], fenc(a.z));
    atomicMax(&g_amax[d * 4 + 3], fenc(a.w));
}

// ---------------- K3b: exp(alpha - max) and denominator ----------------
__global__ void k_exp(const int* __restrict__ ei) {
    int e = blockIdx.x * blockDim.x + threadIdx.x;
    if (e >= TOT) return;
    int d = (e < EE) ? ei[EE + e] : (e - EE);
    float4 a = *(const float4*)&g_alpha[(size_t)e * 4];
    uint4 mu = *(const uint4*)&g_amax[d * 4];
    float e0 = __expf(a.x - fdec(mu.x));
    float e1 = __expf(a.y - fdec(mu.y));
    float e2 = __expf(a.z - fdec(mu.z));
    float e3 = __expf(a.w - fdec(mu.w));
    float4 r; r.x = e0; r.y = e1; r.z = e2; r.w = e3;
    *(float4*)&g_alpha[(size_t)e * 4] = r;
    red2(&g_denom[d * 4],     e0, e1);
    red2(&g_denom[d * 4 + 2], e2, e3);
}

// ---------------- K3c: weighted aggregation, fused head-mean ----------------
__global__ void k_agg(const int* __restrict__ ei) {
    int gw   = (blockIdx.x * blockDim.x + threadIdx.x) >> 5;
    int lane = threadIdx.x & 31;
    if (gw >= TOT) return;
    int s, d;
    if (gw < EE) { s = ei[gw]; d = ei[EE + gw]; }
    else         { s = d = gw - EE; }
    float4 ex = *(const float4*)&g_alpha[(size_t)gw * 4];
    float4 dn = *(const float4*)&g_denom[d * 4];
    float w0 = 0.25f * ex.x / (dn.x + 1e-16f);
    float w1 = 0.25f * ex.y / (dn.y + 1e-16f);
    float w2 = 0.25f * ex.z / (dn.z + 1e-16f);
    float w3 = 0.25f * ex.w / (dn.w + 1e-16f);
    const float* xl = g_xl + (size_t)s * 256;
    int f2 = lane * 2;
    float2 v0 = *(const float2*)(xl + f2);
    float2 v1 = *(const float2*)(xl + 64 + f2);
    float2 v2 = *(const float2*)(xl + 128 + f2);
    float2 v3 = *(const float2*)(xl + 192 + f2);
    float c0 = w0 * v0.x + w1 * v1.x + w2 * v2.x + w3 * v3.x;
    float c1 = w0 * v0.y + w1 * v1.y + w2 * v2.y + w3 * v3.y;
    red2(&g_outpre[d * 64 + f2], c0, c1);
}

// ---------------- K4a: BN statistics ----------------
__global__ void __launch_bounds__(256) k_bnstats(const float* __restrict__ bias) {
    int tid = threadIdx.x;
    int f = tid & 63, rg = tid >> 6;
    float b = bias[f];
    float s = 0.f, s2 = 0.f;
    for (int r = blockIdx.x * 4 + rg; r < NN; r += gridDim.x * 4) {
        float v = g_outpre[r * 64 + f] + b;
        s += v; s2 += v * v;
    }
    __shared__ float sh[2][4][64];
    sh[0][rg][f] = s;
    sh[1][rg][f] = s2;
    __syncthreads();
    if (tid < 64) {
        float ts = sh[0][0][tid] + sh[0][1][tid] + sh[0][2][tid] + sh[0][3][tid];
        float tq = sh[1][0][tid] + sh[1][1][tid] + sh[1][2][tid] + sh[1][3][tid];
        atomicAdd(&g_bnsum[tid], ts);
        atomicAdd(&g_bnsq[tid], tq);
    }
}

// ---------------- K4b: BN apply + ReLU ----------------
__global__ void k_bnapply(const float* __restrict__ bias,
                          const float* __restrict__ gamma,
                          const float* __restrict__ beta,
                          float* __restrict__ out) {
    int i = blockIdx.x * blockDim.x + threadIdx.x;
    if (i >= NN * FF) return;
    int f = i & 63;
    const float invn = 1.0f / (float)NN;
    float mu  = g_bnsum[f] * invn;
    float var = g_bnsq[f] * invn - mu * mu;
    float v = g_outpre[i] + bias[f];
    float o = gamma[f] * (v - mu) * rsqrtf(var + 1e-5f) + beta[f];
    out[i] = (o > 0.f) ? o : 0.f;
}

// ---------------- launch ----------------
extern "C" void kernel_launch(void* const* d_in, const int* in_sizes, int n_in,
                              void* d_out, int out_size) {
    const float* x     = (const float*)d_in[0];
    const int*   ei    = (const int*)d_in[1];
    const float* ea    = (const float*)d_in[2];
    const float* Wl    = (const float*)d_in[3];
    const float* bl    = (const float*)d_in[4];
    const float* Wr    = (const float*)d_in[5];
    const float* br    = (const float*)d_in[6];
    const float* We    = (const float*)d_in[7];
    const float* att   = (const float*)d_in[8];
    const float* bias  = (const float*)d_in[9];
    const float* gamma = (const float*)d_in[10];
    const float* beta  = (const float*)d_in[11];
    float* out = (float*)d_out;

    cudaFuncSetAttribute(k_alpha, cudaFuncAttributeMaxDynamicSharedMemorySize, K3_SMEM);

    k_zero<<<(NN * FF + 255) / 256, 256>>>();

    dim3 g1((NN + 31) / 32, 4);
    k_lin<<<g1, 256>>>(x, Wl, bl, Wr, br);

    k_loopstats<<<(EE * 32 + 255) / 256, 256>>>(ei, ea);

    // local launch index 3 -> ncu's profiled slot
    k_alpha<<<148 * 3 * 2 / 2 * 2, 256, K3_SMEM>>>(ei, ea, We, att); // 888 blocks: 444/half

    k_amax<<<(TOT + 255) / 256, 256>>>(ei);
    k_exp<<<(TOT + 255) / 256, 256>>>(ei);
    k_agg<<<((size_t)TOT * 32 + 255) / 256, 256>>>(ei);

    k_bnstats<<<128, 256>>>(bias);
    k_bnapply<<<(NN * FF + 255) / 256, 256>>>(bias, gamma, beta, out);
}